// round 1
// baseline (speedup 1.0000x reference)
#include <cuda_runtime.h>
#include <cstdint>
#include <math.h>

// Problem constants: B=2, S=2048, D=1024, H=16, hd=64
#define SEQ   2048
#define DMODEL 1024
#define NH    16
#define HD    64
#define MTOT  4096   // B*S

// ---------------- scratch (no cudaMalloc allowed) ----------------
__device__ float g_Q[MTOT * DMODEL];
__device__ float g_K[MTOT * DMODEL];
__device__ float g_V[MTOT * DMODEL];

// ---------------- helpers ----------------
__device__ __forceinline__ uint32_t f2tf(float x) {
    uint32_t u;
    asm("cvt.rna.tf32.f32 %0, %1;" : "=r"(u) : "f"(x));
    return u;
}

__device__ __forceinline__ void mma8(float* c, const uint32_t* a, uint32_t b0, uint32_t b1) {
    asm volatile(
        "mma.sync.aligned.m16n8k8.row.col.f32.tf32.tf32.f32 "
        "{%0,%1,%2,%3}, {%4,%5,%6,%7}, {%8,%9}, {%0,%1,%2,%3};"
        : "+f"(c[0]), "+f"(c[1]), "+f"(c[2]), "+f"(c[3])
        : "r"(a[0]), "r"(a[1]), "r"(a[2]), "r"(a[3]), "r"(b0), "r"(b1));
}

// ======================================================================
// Kernel 1: QKV projection GEMM.  C[4096,1024] = x[4096,1024] @ W[1024,1024] + b
// blockIdx.z selects (Wq->g_Q, Wk->g_K, Wv->g_V).
// Block tile 128x128, K-tile 32. 256 threads = 8 warps in 4(m) x 2(n).
// Warp tile 32x64 -> 2 m16 tiles x 8 n8 tiles of m16n8k8 tf32 mma.
// ======================================================================
__global__ __launch_bounds__(256) void qkv_gemm(
    const float* __restrict__ x,
    const float* __restrict__ Wq, const float* __restrict__ Wk, const float* __restrict__ Wv,
    const float* __restrict__ bq, const float* __restrict__ bk, const float* __restrict__ bv)
{
    __shared__ float As[128][36];   // pad 36: frag bank = (4g+t)%32, conflict-free
    __shared__ float Bs[32][136];   // pad 136: frag bank = (8t+g)%32, conflict-free

    const float* W; const float* bias; float* outp;
    if (blockIdx.z == 0)      { W = Wq; bias = bq; outp = g_Q; }
    else if (blockIdx.z == 1) { W = Wk; bias = bk; outp = g_K; }
    else                      { W = Wv; bias = bv; outp = g_V; }

    const int tid  = threadIdx.x;
    const int warp = tid >> 5, lane = tid & 31;
    const int g = lane >> 2, t = lane & 3;
    const int wr = warp >> 1;          // 0..3 (m)
    const int wc = warp & 1;           // 0..1 (n)
    const int m0 = blockIdx.y * 128;
    const int n0 = blockIdx.x * 128;

    float acc[2][8][4] = {};

    for (int k0 = 0; k0 < DMODEL; k0 += 32) {
        // load A tile 128x32 (convert fp32 -> tf32 once)
        #pragma unroll
        for (int r = 0; r < 4; r++) {
            int i = tid + 256 * r;           // 0..1023
            int row = i >> 3;
            int c4  = (i & 7) << 2;
            float4 v = *(const float4*)&x[(m0 + row) * DMODEL + k0 + c4];
            As[row][c4 + 0] = __uint_as_float(f2tf(v.x));
            As[row][c4 + 1] = __uint_as_float(f2tf(v.y));
            As[row][c4 + 2] = __uint_as_float(f2tf(v.z));
            As[row][c4 + 3] = __uint_as_float(f2tf(v.w));
        }
        // load B tile 32x128
        #pragma unroll
        for (int r = 0; r < 4; r++) {
            int i = tid + 256 * r;
            int row = i >> 5;
            int c4  = (i & 31) << 2;
            float4 v = *(const float4*)&W[(k0 + row) * DMODEL + n0 + c4];
            Bs[row][c4 + 0] = __uint_as_float(f2tf(v.x));
            Bs[row][c4 + 1] = __uint_as_float(f2tf(v.y));
            Bs[row][c4 + 2] = __uint_as_float(f2tf(v.z));
            Bs[row][c4 + 3] = __uint_as_float(f2tf(v.w));
        }
        __syncthreads();

        #pragma unroll
        for (int ks = 0; ks < 4; ks++) {
            const int kk = ks * 8;
            uint32_t a[2][4], bb[8][2];
            #pragma unroll
            for (int mt = 0; mt < 2; mt++) {
                int rb = wr * 32 + mt * 16;
                a[mt][0] = __float_as_uint(As[rb + g    ][kk + t    ]);
                a[mt][1] = __float_as_uint(As[rb + g + 8][kk + t    ]);
                a[mt][2] = __float_as_uint(As[rb + g    ][kk + t + 4]);
                a[mt][3] = __float_as_uint(As[rb + g + 8][kk + t + 4]);
            }
            #pragma unroll
            for (int nt = 0; nt < 8; nt++) {
                int cb = wc * 64 + nt * 8;
                bb[nt][0] = __float_as_uint(Bs[kk + t    ][cb + g]);
                bb[nt][1] = __float_as_uint(Bs[kk + t + 4][cb + g]);
            }
            #pragma unroll
            for (int mt = 0; mt < 2; mt++)
                #pragma unroll
                for (int nt = 0; nt < 8; nt++)
                    mma8(acc[mt][nt], a[mt], bb[nt][0], bb[nt][1]);
        }
        __syncthreads();
    }

    // epilogue: + bias, write row-major
    #pragma unroll
    for (int mt = 0; mt < 2; mt++) {
        int row = m0 + wr * 32 + mt * 16 + g;
        #pragma unroll
        for (int nt = 0; nt < 8; nt++) {
            int col = n0 + wc * 64 + nt * 8 + 2 * t;
            float b0v = bias[col], b1v = bias[col + 1];
            float2 v0 = make_float2(acc[mt][nt][0] + b0v, acc[mt][nt][1] + b1v);
            float2 v1 = make_float2(acc[mt][nt][2] + b0v, acc[mt][nt][3] + b1v);
            *(float2*)&outp[(size_t)row       * DMODEL + col] = v0;
            *(float2*)&outp[(size_t)(row + 8) * DMODEL + col] = v1;
        }
    }
}

// ======================================================================
// Kernel 2: flash attention.  grid = (SEQ/64, B*NH), 128 threads (4 warps).
// Each warp owns 16 query rows x all keys => softmax row stats reduce
// inside a quad (lanes sharing groupID). KV tiles of 32 keys.
// ======================================================================
__global__ __launch_bounds__(128) void attn_kernel(float* __restrict__ out)
{
    __shared__ float Ks[32][68];   // frag bank (4g+t)%32 conflict-free
    __shared__ float Vs[32][72];   // frag bank (8t+g)%32 conflict-free
    __shared__ float Ps[64][36];   // frag bank (4g+t)%32 conflict-free

    const int tid = threadIdx.x, warp = tid >> 5, lane = tid & 31;
    const int g = lane >> 2, t = lane & 3;
    const int bh = blockIdx.y;
    const int b  = bh >> 4;
    const int h  = bh & 15;
    const int q0 = blockIdx.x * 64;

    // --- load Q fragments for this warp's 16 rows directly from global ---
    const int qrow = b * SEQ + q0 + warp * 16;
    uint32_t qa[8][4];
    #pragma unroll
    for (int kt = 0; kt < 8; kt++) {
        qa[kt][0] = f2tf(g_Q[(qrow + g    ) * DMODEL + h * HD + kt * 8 + t    ]);
        qa[kt][1] = f2tf(g_Q[(qrow + g + 8) * DMODEL + h * HD + kt * 8 + t    ]);
        qa[kt][2] = f2tf(g_Q[(qrow + g    ) * DMODEL + h * HD + kt * 8 + t + 4]);
        qa[kt][3] = f2tf(g_Q[(qrow + g + 8) * DMODEL + h * HD + kt * 8 + t + 4]);
    }

    float m2[2]  = {-INFINITY, -INFINITY};   // running max (log2 domain)
    float ls[2]  = {0.f, 0.f};               // per-lane partial row sums
    float o[8][4] = {};

    const int kvbase = b * SEQ;
    const float SC = 0.125f * 1.44269504088896f;  // 1/sqrt(64) * log2(e)

    for (int kv0 = 0; kv0 < SEQ; kv0 += 32) {
        // --- load K,V tiles (32 keys x 64 dims), convert to tf32 ---
        #pragma unroll
        for (int r = 0; r < 4; r++) {
            int i = tid + 128 * r;       // 0..511
            int row = i >> 4;
            int c4  = (i & 15) << 2;
            int gidx = (kvbase + kv0 + row) * DMODEL + h * HD + c4;
            float4 kv = *(const float4*)&g_K[gidx];
            Ks[row][c4 + 0] = __uint_as_float(f2tf(kv.x));
            Ks[row][c4 + 1] = __uint_as_float(f2tf(kv.y));
            Ks[row][c4 + 2] = __uint_as_float(f2tf(kv.z));
            Ks[row][c4 + 3] = __uint_as_float(f2tf(kv.w));
            float4 vv = *(const float4*)&g_V[gidx];
            Vs[row][c4 + 0] = __uint_as_float(f2tf(vv.x));
            Vs[row][c4 + 1] = __uint_as_float(f2tf(vv.y));
            Vs[row][c4 + 2] = __uint_as_float(f2tf(vv.z));
            Vs[row][c4 + 3] = __uint_as_float(f2tf(vv.w));
        }
        __syncthreads();

        // --- S = Q @ K^T ---
        float s[4][4] = {};
        #pragma unroll
        for (int nt = 0; nt < 4; nt++) {
            #pragma unroll
            for (int kt = 0; kt < 8; kt++) {
                uint32_t b0 = __float_as_uint(Ks[nt * 8 + g][kt * 8 + t    ]);
                uint32_t b1 = __float_as_uint(Ks[nt * 8 + g][kt * 8 + t + 4]);
                mma8(s[nt], qa[kt], b0, b1);
            }
        }

        // --- scale into log2 domain, row max (over this tile) ---
        float mx0 = -INFINITY, mx1 = -INFINITY;
        #pragma unroll
        for (int nt = 0; nt < 4; nt++) {
            s[nt][0] *= SC; s[nt][1] *= SC; s[nt][2] *= SC; s[nt][3] *= SC;
            mx0 = fmaxf(mx0, fmaxf(s[nt][0], s[nt][1]));
            mx1 = fmaxf(mx1, fmaxf(s[nt][2], s[nt][3]));
        }
        mx0 = fmaxf(mx0, __shfl_xor_sync(0xffffffffu, mx0, 1));
        mx0 = fmaxf(mx0, __shfl_xor_sync(0xffffffffu, mx0, 2));
        mx1 = fmaxf(mx1, __shfl_xor_sync(0xffffffffu, mx1, 1));
        mx1 = fmaxf(mx1, __shfl_xor_sync(0xffffffffu, mx1, 2));

        float mn0 = fmaxf(m2[0], mx0);
        float mn1 = fmaxf(m2[1], mx1);
        float c0 = exp2f(m2[0] - mn0);
        float c1 = exp2f(m2[1] - mn1);
        m2[0] = mn0; m2[1] = mn1;
        ls[0] *= c0; ls[1] *= c1;
        #pragma unroll
        for (int nt = 0; nt < 8; nt++) {
            o[nt][0] *= c0; o[nt][1] *= c0;
            o[nt][2] *= c1; o[nt][3] *= c1;
        }

        // --- P = exp2(s - m), stash to smem as tf32 for re-fragmenting ---
        #pragma unroll
        for (int nt = 0; nt < 4; nt++) {
            float p0 = exp2f(s[nt][0] - mn0);
            float p1 = exp2f(s[nt][1] - mn0);
            float p2 = exp2f(s[nt][2] - mn1);
            float p3 = exp2f(s[nt][3] - mn1);
            ls[0] += p0 + p1;
            ls[1] += p2 + p3;
            Ps[warp * 16 + g    ][nt * 8 + 2 * t    ] = __uint_as_float(f2tf(p0));
            Ps[warp * 16 + g    ][nt * 8 + 2 * t + 1] = __uint_as_float(f2tf(p1));
            Ps[warp * 16 + g + 8][nt * 8 + 2 * t    ] = __uint_as_float(f2tf(p2));
            Ps[warp * 16 + g + 8][nt * 8 + 2 * t + 1] = __uint_as_float(f2tf(p3));
        }
        __syncwarp();

        // --- O += P @ V ---
        uint32_t pa[4][4];
        #pragma unroll
        for (int kt = 0; kt < 4; kt++) {
            pa[kt][0] = __float_as_uint(Ps[warp * 16 + g    ][kt * 8 + t    ]);
            pa[kt][1] = __float_as_uint(Ps[warp * 16 + g + 8][kt * 8 + t    ]);
            pa[kt][2] = __float_as_uint(Ps[warp * 16 + g    ][kt * 8 + t + 4]);
            pa[kt][3] = __float_as_uint(Ps[warp * 16 + g + 8][kt * 8 + t + 4]);
        }
        #pragma unroll
        for (int nt = 0; nt < 8; nt++) {
            #pragma unroll
            for (int kt = 0; kt < 4; kt++) {
                uint32_t b0 = __float_as_uint(Vs[kt * 8 + t    ][nt * 8 + g]);
                uint32_t b1 = __float_as_uint(Vs[kt * 8 + t + 4][nt * 8 + g]);
                mma8(o[nt], pa[kt], b0, b1);
            }
        }
        __syncthreads();
    }

    // --- normalize and write out[b, s, h*64 + d] ---
    ls[0] += __shfl_xor_sync(0xffffffffu, ls[0], 1);
    ls[0] += __shfl_xor_sync(0xffffffffu, ls[0], 2);
    ls[1] += __shfl_xor_sync(0xffffffffu, ls[1], 1);
    ls[1] += __shfl_xor_sync(0xffffffffu, ls[1], 2);
    float i0 = 1.f / ls[0];
    float i1 = 1.f / ls[1];

    const int orow = b * SEQ + q0 + warp * 16;
    #pragma unroll
    for (int nt = 0; nt < 8; nt++) {
        int col = h * HD + nt * 8 + 2 * t;
        float2 v0 = make_float2(o[nt][0] * i0, o[nt][1] * i0);
        float2 v1 = make_float2(o[nt][2] * i1, o[nt][3] * i1);
        *(float2*)&out[(size_t)(orow + g    ) * DMODEL + col] = v0;
        *(float2*)&out[(size_t)(orow + g + 8) * DMODEL + col] = v1;
    }
}

// ======================================================================
// launch
// ======================================================================
extern "C" void kernel_launch(void* const* d_in, const int* in_sizes, int n_in,
                              void* d_out, int out_size)
{
    const float* x  = (const float*)d_in[0];
    const float* Wq = (const float*)d_in[1];
    const float* bq = (const float*)d_in[2];
    const float* Wk = (const float*)d_in[3];
    const float* bk = (const float*)d_in[4];
    const float* Wv = (const float*)d_in[5];
    const float* bv = (const float*)d_in[6];
    float* out = (float*)d_out;

    dim3 gg(DMODEL / 128, MTOT / 128, 3);   // (8, 32, 3)
    qkv_gemm<<<gg, 256>>>(x, Wq, Wk, Wv, bq, bk, bv);

    dim3 ga(SEQ / 64, 2 * NH);              // (32, 32)
    attn_kernel<<<ga, 128>>>(out);
}